// round 12
// baseline (speedup 1.0000x reference)
#include <cuda_runtime.h>

// GenLoss, fused single kernel, EXACTLY per-SM-balanced grid (740 = 148*5).
// combined = mean_b( masked-mean_c( MAE(out,target)[b,c] ) ) - 0.01*mean(labels)/(epoch+1)
//
// R9's proven protocol (one-shot RED arrival counter + single-thread 128ns
// poll + fixed-order finalize) with one change: grid is 740 blocks so every
// SM holds exactly 5 (R9's 776 gave 36 SMs six blocks -> ~20% straggler SMs
// that the finalizer had to wait out). Workers split the flat chunk space
// (48 planes x 256 chunks of 1024 elems) 17/16 chunks each and accumulate
// per-plane via one-shot atomicAdd/atomicOr (16 ops/address, RED-cheap;
// float-order noise ~1e-7 << 1e-3 tolerance). Finalizer block also does the
// label sum BEFORE polling (overlapped with the stream), then folds 48 plane
// sums and resets all state for graph replay.

#define PLANES    48
#define NCHUNK    (PLANES * 256)   // 12288 chunks of 1024 elems
#define WORKERS   739
#define TOTAL_BLK 740              // 148 SMs * 5 blocks
#define FIN_BLK   (TOTAL_BLK - 1)
#define THREADS   256
#define CPB       16               // base chunks per worker
#define REM       (NCHUNK - WORKERS * CPB)   // 464 workers get one extra

__device__ float g_plane_sum[PLANES];   // zero-init; reset by finalizer
__device__ int   g_plane_flag[PLANES];  // zero-init; reset by finalizer
__device__ int   g_done;                // zero-init; reset by finalizer

__global__ void __launch_bounds__(THREADS, 8)
k_genloss(const float* __restrict__ out_img, const float* __restrict__ tgt_img,
          const float* __restrict__ labels, int n_labels,
          const int* __restrict__ epoch, float* __restrict__ out)
{
    const int tid = threadIdx.x;
    const int wid = tid >> 5;
    const int lid = tid & 31;
    const int bid = blockIdx.x;

    __shared__ float ss0[THREADS / 32], ss1[THREADS / 32];
    __shared__ int   sf0[THREADS / 32], sf1[THREADS / 32];

    if (bid < WORKERS) {
        // ---- image MAE over a contiguous run of 16 or 17 chunks ----
        const int extra = (bid < REM) ? 1 : 0;
        const int start = bid * CPB + (bid < REM ? bid : REM);
        const int n     = CPB + extra;
        const int p0    = start >> 8;            // first plane touched
        // a run of <=17 chunks spans at most 2 planes (256 chunks/plane)

        const float4* __restrict__ o4 = (const float4*)out_img;
        const float4* __restrict__ t4 = (const float4*)tgt_img;

        float s0 = 0.0f, s1 = 0.0f;
        int   f0 = 0,    f1 = 0;
        #pragma unroll 4
        for (int k = 0; k < n; k++) {
            const int  c   = start + k;
            const long idx = (long)c * 256 + tid;
            float4 a = o4[idx];
            float4 b = t4[idx];
            float d = fabsf(a.x - b.x) + fabsf(a.y - b.y)
                    + fabsf(a.z - b.z) + fabsf(a.w - b.w);
            int  fl = (b.x != 0.0f) | (b.y != 0.0f) | (b.z != 0.0f) | (b.w != 0.0f);
            if ((c >> 8) == p0) { s0 += d; f0 |= fl; }
            else                { s1 += d; f1 |= fl; }
        }
        #pragma unroll
        for (int off = 16; off; off >>= 1) {
            s0 += __shfl_down_sync(0xffffffffu, s0, off);
            s1 += __shfl_down_sync(0xffffffffu, s1, off);
            f0 |= __shfl_down_sync(0xffffffffu, f0, off);
            f1 |= __shfl_down_sync(0xffffffffu, f1, off);
        }
        if (lid == 0) { ss0[wid] = s0; ss1[wid] = s1; sf0[wid] = f0; sf1[wid] = f1; }
        __syncthreads();
        if (tid == 0) {
            float b0 = 0.0f, b1 = 0.0f; int bf0 = 0, bf1 = 0;
            #pragma unroll
            for (int w = 0; w < THREADS / 32; w++) {
                b0 += ss0[w]; b1 += ss1[w]; bf0 |= sf0[w]; bf1 |= sf1[w];
            }
            atomicAdd(&g_plane_sum[p0], b0);      // one-shot RED
            if (bf0) atomicOr(&g_plane_flag[p0], 1);
            const int plast = (start + n - 1) >> 8;
            if (plast != p0) {
                atomicAdd(&g_plane_sum[plast], b1);
                if (bf1) atomicOr(&g_plane_flag[plast], 1);
            }
            __threadfence();
            atomicAdd(&g_done, 1);                // arrival (fire-and-forget)
        }
        return;
    }

    // ================= block 739: labels (overlapped) + finalizer =================
    __shared__ float slab;
    {
        float s = 0.0f;
        for (int i = tid; i < n_labels; i += THREADS) s += labels[i];
        #pragma unroll
        for (int off = 16; off; off >>= 1)
            s += __shfl_down_sync(0xffffffffu, s, off);
        if (lid == 0) ss0[wid] = s;
        __syncthreads();
        if (tid == 0) {
            float bs = 0.0f;
            #pragma unroll
            for (int w = 0; w < THREADS / 32; w++) bs += ss0[w];
            slab = bs;
        }
    }

    // single-thread low-pressure poll (R8 lesson: heavy polling starves the SM)
    if (tid == 0) {
        volatile int* vd = &g_done;
        while (*vd != WORKERS) __nanosleep(128);
        g_done = 0;                                // reset for next replay
    }
    __syncthreads();
    __threadfence();   // acquire: order plane reads after counter observation

    __shared__ float sps[PLANES];
    __shared__ int   spv[PLANES];
    if (tid < PLANES) {
        sps[tid] = g_plane_sum[tid];
        spv[tid] = g_plane_flag[tid];
    }
    __syncthreads();
    // reset accumulators for next graph replay (reads above are complete)
    if (tid < PLANES) {
        g_plane_sum[tid]  = 0.0f;
        g_plane_flag[tid] = 0;
    }

    if (tid == 0) {
        const float lmean = slab / (float)n_labels;

        float img = 0.0f;
        #pragma unroll
        for (int b = 0; b < 16; b++) {
            float tot = 0.0f, cnt = 0.0f;
            #pragma unroll
            for (int c = 0; c < 3; c++) {
                const int p = b * 3 + c;
                if (spv[p]) { tot += sps[p] * (1.0f / (float)(512*512)); cnt += 1.0f; }
            }
            img += (cnt > 0.0f) ? (tot / cnt) : 0.0f;
        }
        img *= (1.0f / 16.0f);

        out[0] = img + 0.01f * (-lmean) / (float)(epoch[0] + 1);
    }
}

extern "C" void kernel_launch(void* const* d_in, const int* in_sizes, int n_in,
                              void* d_out, int out_size)
{
    const float* labels  = (const float*)d_in[0];
    const float* out_img = (const float*)d_in[1];
    const float* tgt_img = (const float*)d_in[2];
    const int*   epoch   = (const int*)d_in[3];
    float*       out     = (float*)d_out;

    k_genloss<<<TOTAL_BLK, THREADS>>>(out_img, tgt_img, labels, in_sizes[0], epoch, out);
}

// round 13
// speedup vs baseline: 1.0913x; 1.0913x over previous
#include <cuda_runtime.h>

// GenLoss, fused single kernel (R9 protocol, proven 14.8us) with two deltas:
//  (1) __launch_bounds__(256,6) instead of (256,8): lifts the 32-reg cap so
//      ptxas can front-batch ~2x more LDG.128s -> more outstanding HBM reads.
//      The timed replays are HBM-bound (14.8us = 6.8TB/s = 85% of spec), so
//      MLP is the remaining lever. 148*6=888 >= 776 -> still one wave.
//  (2) finalizer poll quantum 1000ns -> 256ns (single-thread poll; R8 showed
//      multi-thread polling starves the SM, one thread at 256ns is free).
// combined = mean_b( masked-mean_c( MAE(out,target)[b,c] ) ) - 0.01*mean(labels)/(epoch+1)

#define PLANES      48
#define BPP         16
#define RBLOCKS     (PLANES * BPP)      // 768
#define LBLOCKS     8
#define TOTAL_BLK   (RBLOCKS + LBLOCKS) // 776
#define FIN_BLK     (TOTAL_BLK - 1)
#define THREADS     256
#define PLANE_ELEMS (512*512)
#define BLOCK_ELEMS (PLANE_ELEMS/BPP)          // 16384
#define VEC_ITERS   (BLOCK_ELEMS/(THREADS*4))  // 16

__device__ float g_psum[RBLOCKS];
__device__ int   g_pflag[RBLOCKS];
__device__ float g_lsum[LBLOCKS];
__device__ int   g_done;               // zero-init; reset by finalizer each run

__global__ void __launch_bounds__(THREADS, 6)
k_genloss(const float* __restrict__ out_img, const float* __restrict__ tgt_img,
          const float* __restrict__ labels, int n_labels,
          const int* __restrict__ epoch, float* __restrict__ out)
{
    const int tid = threadIdx.x;
    const int wid = tid >> 5;
    const int lid = tid & 31;
    const int bid = blockIdx.x;

    __shared__ float ss[THREADS / 32];
    __shared__ int   sf[THREADS / 32];

    if (bid < RBLOCKS) {
        // ---- image MAE partial over 1/16th of one plane ----
        const int plane = bid / BPP;
        const int sub   = bid % BPP;
        const long base = (long)plane * PLANE_ELEMS + (long)sub * BLOCK_ELEMS;

        const float4* __restrict__ o = (const float4*)(out_img + base);
        const float4* __restrict__ t = (const float4*)(tgt_img + base);

        float s = 0.0f;
        int   flag = 0;
        #pragma unroll
        for (int j = 0; j < VEC_ITERS; j++) {
            float4 a = o[tid + j * THREADS];
            float4 b = t[tid + j * THREADS];
            s += fabsf(a.x - b.x) + fabsf(a.y - b.y)
               + fabsf(a.z - b.z) + fabsf(a.w - b.w);
            flag |= (b.x != 0.0f) | (b.y != 0.0f) | (b.z != 0.0f) | (b.w != 0.0f);
        }
        #pragma unroll
        for (int off = 16; off; off >>= 1) {
            s    += __shfl_down_sync(0xffffffffu, s, off);
            flag |= __shfl_down_sync(0xffffffffu, flag, off);
        }
        if (lid == 0) { ss[wid] = s; sf[wid] = flag; }
        __syncthreads();
        if (tid == 0) {
            float bs = 0.0f; int bf = 0;
            #pragma unroll
            for (int w = 0; w < THREADS / 32; w++) { bs += ss[w]; bf |= sf[w]; }
            g_psum[bid]  = bs;
            g_pflag[bid] = bf;
            __threadfence();
            atomicAdd(&g_done, 1);    // fire-and-forget (RED), one-shot
        }
        return;
    }

    // ---- label partial sum (blocks 768..775) ----
    const int lb = bid - RBLOCKS;
    {
        float s = 0.0f;
        for (int i = lb * THREADS + tid; i < n_labels; i += LBLOCKS * THREADS)
            s += labels[i];
        #pragma unroll
        for (int off = 16; off; off >>= 1)
            s += __shfl_down_sync(0xffffffffu, s, off);
        if (lid == 0) ss[wid] = s;
        __syncthreads();
        if (tid == 0) {
            float bs = 0.0f;
            #pragma unroll
            for (int w = 0; w < THREADS / 32; w++) bs += ss[w];
            g_lsum[lb] = bs;
            if (bid != FIN_BLK) {
                __threadfence();
                atomicAdd(&g_done, 1);
            }
        }
    }
    if (bid != FIN_BLK) return;

    // ================= finalizer (block 775) =================
    if (tid == 0) {
        volatile int* vd = &g_done;
        while (*vd != TOTAL_BLK - 1) __nanosleep(256);
    }
    __syncthreads();
    __threadfence();   // acquire: order partial reads after counter observation

    __shared__ float sp[RBLOCKS];
    __shared__ int   sfl[RBLOCKS];
    __shared__ float plane_mae[PLANES];
    __shared__ int   plane_valid[PLANES];

    // Parallel vectorized fetch of partials (one L2 latency round-trip).
    const float4* ps4 = (const float4*)g_psum;
    const int4*   pf4 = (const int4*)g_pflag;
    if (tid < RBLOCKS / 4) {
        float4 v = ps4[tid];
        int4   f = pf4[tid];
        sp[tid * 4 + 0] = v.x;  sp[tid * 4 + 1] = v.y;
        sp[tid * 4 + 2] = v.z;  sp[tid * 4 + 3] = v.w;
        sfl[tid * 4 + 0] = f.x; sfl[tid * 4 + 1] = f.y;
        sfl[tid * 4 + 2] = f.z; sfl[tid * 4 + 3] = f.w;
    }
    __syncthreads();

    if (tid < PLANES) {
        float s = 0.0f; int f = 0;
        #pragma unroll
        for (int i = 0; i < BPP; i++) {
            s += sp[tid * BPP + i];
            f |= sfl[tid * BPP + i];
        }
        plane_mae[tid]   = s * (1.0f / (float)PLANE_ELEMS);
        plane_valid[tid] = f;
    }
    __syncthreads();

    if (tid == 0) {
        float lsum = 0.0f;
        #pragma unroll
        for (int i = 0; i < LBLOCKS; i++) lsum += g_lsum[i];
        const float lmean = lsum / (float)n_labels;

        float img = 0.0f;
        #pragma unroll
        for (int b = 0; b < 16; b++) {
            float tot = 0.0f, cnt = 0.0f;
            #pragma unroll
            for (int c = 0; c < 3; c++) {
                const int p = b * 3 + c;
                if (plane_valid[p]) { tot += plane_mae[p]; cnt += 1.0f; }
            }
            img += (cnt > 0.0f) ? (tot / cnt) : 0.0f;
        }
        img *= (1.0f / 16.0f);

        out[0] = img + 0.01f * (-lmean) / (float)(epoch[0] + 1);
        g_done = 0;    // reset for next graph replay (all adds already observed)
    }
}

extern "C" void kernel_launch(void* const* d_in, const int* in_sizes, int n_in,
                              void* d_out, int out_size)
{
    const float* labels  = (const float*)d_in[0];
    const float* out_img = (const float*)d_in[1];
    const float* tgt_img = (const float*)d_in[2];
    const int*   epoch   = (const int*)d_in[3];
    float*       out     = (float*)d_out;

    k_genloss<<<TOTAL_BLK, THREADS>>>(out_img, tgt_img, labels, in_sizes[0], epoch, out);
}